// round 13
// baseline (speedup 1.0000x reference)
#include <cuda_runtime.h>
#include <cuda_bf16.h>
#include <cuda_fp16.h>
#include <mma.h>
#include <cstdint>
#include <cstddef>

using namespace nvcuda;

#define FDIM 128
#define KDIM 64
#define CDIM 256
#define MNBR 12
#define NMAX 100000
#define NEDGE (NMAX * MNBR)

typedef __nv_bfloat16 bf16;

__device__ float  g_Pself[(size_t)NMAX * CDIM];
__device__ float  g_Pnbr [(size_t)NMAX * CDIM];
__device__ __half g_Pnbrh[(size_t)NMAX * CDIM];
__device__ __half g_gatedh[(size_t)NEDGE * CDIM];
__device__ float  g_nbrsum[(size_t)NMAX * FDIM];
__device__ int    g_idx32[NEDGE];
__device__ float  g_sum1[CDIM], g_sq1[CDIM], g_scale1[CDIM], g_shift1[CDIM];
__device__ float  g_sum2[FDIM], g_sq2[FDIM], g_scale2[FDIM], g_shift2[FDIM];

__device__ __forceinline__ void split2(float a, float b, uint32_t& hi, uint32_t& lo) {
    __nv_bfloat162 H, L;
    H.x = __float2bfloat16(a); H.y = __float2bfloat16(b);
    L.x = __float2bfloat16(a - __bfloat162float(H.x));
    L.y = __float2bfloat16(b - __bfloat162float(H.y));
    hi = *(uint32_t*)&H; lo = *(uint32_t*)&L;
}

// ---- K0: zero stats + normalize indices to int32 (per-block dtype detect) ---
__global__ void k_init(const void* __restrict__ raw, int total) {
    __shared__ int s64;
    const int tid = threadIdx.x;
    if (tid == 0) {
        const int* w = (const int*)raw;
        int nz = 0;
        #pragma unroll 4
        for (int i = 1; i < 128; i += 2) nz |= (w[i] != 0);
        s64 = nz ? 0 : 1;
    }
    __syncthreads();
    int i = blockIdx.x * blockDim.x + tid;
    if (i < total)
        g_idx32[i] = s64 ? (int)((const long long*)raw)[i] : ((const int*)raw)[i];
    if (blockIdx.x == 0) {
        if (tid < CDIM) { g_sum1[tid] = 0.f; g_sq1[tid] = 0.f; }
        if (tid < FDIM) { g_sum2[tid] = 0.f; g_sq2[tid] = 0.f; }
    }
}

// ---- K1: projection GEMMs. grid (ceil(N/128), 2). 512 thr; warp = (atile, nhalf).
#define PLD 136
__global__ void __launch_bounds__(512) k_proj(const float* __restrict__ atom,
                                              const float* __restrict__ W, int N) {
    extern __shared__ __align__(16) char smem[];
    bf16* sAh = (bf16*)smem;
    bf16* sAl = sAh + 128 * PLD;
    bf16* sWh = sAl + 128 * PLD;
    bf16* sWl = sWh + 256 * PLD;
    const int tid = threadIdx.x, wid = tid >> 5;
    const int part = blockIdx.y, n0 = blockIdx.x * 128;

    {   // A: row = tid/4, quarter = tid&3
        int row = tid >> 2, q = tid & 3, n = n0 + row;
        #pragma unroll
        for (int i = 0; i < 8; i++) {
            float4 v = (n < N) ? *(const float4*)(atom + (size_t)n * FDIM + q * 32 + i * 4)
                               : make_float4(0.f, 0.f, 0.f, 0.f);
            int k = q * 32 + i * 4;
            uint32_t h0, l0, h1, l1;
            split2(v.x, v.y, h0, l0); split2(v.z, v.w, h1, l1);
            *(uint32_t*)(sAh + row * PLD + k)     = h0;
            *(uint32_t*)(sAh + row * PLD + k + 2) = h1;
            *(uint32_t*)(sAl + row * PLD + k)     = l0;
            *(uint32_t*)(sAl + row * PLD + k + 2) = l1;
        }
    }
    {   // W: row = tid/2, half = tid&1
        int wr = tid >> 1, hf = tid & 1;
        const float* wp = W + (size_t)wr * 320 + part * 128 + hf * 64;
        #pragma unroll
        for (int i = 0; i < 16; i++) {
            float4 v = *(const float4*)(wp + i * 4);
            int k = hf * 64 + i * 4;
            uint32_t h0, l0, h1, l1;
            split2(v.x, v.y, h0, l0); split2(v.z, v.w, h1, l1);
            *(uint32_t*)(sWh + wr * PLD + k)     = h0;
            *(uint32_t*)(sWh + wr * PLD + k + 2) = h1;
            *(uint32_t*)(sWl + wr * PLD + k)     = l0;
            *(uint32_t*)(sWl + wr * PLD + k + 2) = l1;
        }
    }
    __syncthreads();

    const int atile = wid >> 1, nh = wid & 1;
    const int nbase = n0 + atile * 16;
    if (nbase >= N) return;
    float* outp = (part ? g_Pnbr : g_Pself) + (size_t)nbase * CDIM + nh * 128;

    wmma::fragment<wmma::matrix_a, 16, 16, 16, bf16, wmma::row_major> ah[8], al;
    wmma::fragment<wmma::matrix_b, 16, 16, 16, bf16, wmma::col_major> bh, bl;
    wmma::fragment<wmma::accumulator, 16, 16, 16, float> acc;
    #pragma unroll
    for (int ks = 0; ks < 8; ks++)
        wmma::load_matrix_sync(ah[ks], sAh + atile * 16 * PLD + ks * 16, PLD);
    #pragma unroll 1
    for (int nt = 0; nt < 8; nt++) {
        wmma::fill_fragment(acc, 0.f);
        #pragma unroll
        for (int ks = 0; ks < 8; ks++) {
            const int nc = (nh * 128 + nt * 16) * PLD + ks * 16;
            wmma::load_matrix_sync(bh, sWh + nc, PLD);
            wmma::load_matrix_sync(bl, sWl + nc, PLD);
            wmma::load_matrix_sync(al, sAl + atile * 16 * PLD + ks * 16, PLD);
            wmma::mma_sync(acc, ah[ks], bh, acc);
            wmma::mma_sync(acc, ah[ks], bl, acc);
            wmma::mma_sync(acc, al, bh, acc);
        }
        wmma::store_matrix_sync(outp + nt * 16, acc, CDIM, wmma::mem_row_major);
    }
}

// ---- K1b: convert Pnbr to fp16 ----------------------------------------------
__global__ void k_cvt(int total4) {
    int i = blockIdx.x * blockDim.x + threadIdx.x;
    if (i < total4) {
        float4 v = ((const float4*)g_Pnbr)[i];
        __half2 h0 = __floats2half2_rn(v.x, v.y), h1 = __floats2half2_rn(v.z, v.w);
        uint2 u; u.x = *(uint32_t*)&h0; u.y = *(uint32_t*)&h1;
        ((uint2*)g_Pnbrh)[i] = u;
    }
}

// ---- K2: edge GEMM + prefetched gathers + gated + BN1 stats. 512 thr. -------
#define ELD 72
#define SLD 68
#define OWH 73728
#define OWL 110592
#define OBI 147456
#define OIX 148480
#define SME 149504
__global__ void __launch_bounds__(512) k_edge(const float* __restrict__ nbr,
                                              const float* __restrict__ W,
                                              const float* __restrict__ bias,
                                              int N, int Ntot) {
    extern __shared__ __align__(16) char smem[];
    bf16*  sAh = (bf16*)smem;                 // 256 x 72 (reused as stg after frags)
    bf16*  sAl = sAh + 256 * ELD;
    bf16*  sWh = (bf16*)(smem + OWH);
    bf16*  sWl = (bf16*)(smem + OWL);
    float* sB  = (float*)(smem + OBI);
    int*   sIdx = (int*)(smem + OIX);
    const int tid = threadIdx.x, wid = tid >> 5, lane = tid & 31;
    const int e0 = blockIdx.x * 256;

    if (tid < 256) {
        sIdx[tid] = (e0 + tid < Ntot) ? g_idx32[e0 + tid] : 0;
        sB[tid] = bias[tid];
    }
    {   // A: edge features
        int row = tid >> 1, kh = tid & 1, e = e0 + row;
        #pragma unroll
        for (int i = 0; i < 8; i++) {
            float4 v = (e < Ntot) ? *(const float4*)(nbr + (size_t)e * KDIM + kh * 32 + i * 4)
                                  : make_float4(0.f, 0.f, 0.f, 0.f);
            int k = kh * 32 + i * 4;
            uint32_t h0, l0, h1, l1;
            split2(v.x, v.y, h0, l0); split2(v.z, v.w, h1, l1);
            *(uint32_t*)(sAh + row * ELD + k)     = h0;
            *(uint32_t*)(sAh + row * ELD + k + 2) = h1;
            *(uint32_t*)(sAl + row * ELD + k)     = l0;
            *(uint32_t*)(sAl + row * ELD + k + 2) = l1;
        }
    }
    {   // W3 rows
        int wr = tid >> 1, kh = tid & 1;
        const float* wp = W + (size_t)wr * 320 + 256 + kh * 32;
        #pragma unroll
        for (int i = 0; i < 8; i++) {
            float4 v = *(const float4*)(wp + i * 4);
            int k = kh * 32 + i * 4;
            uint32_t h0, l0, h1, l1;
            split2(v.x, v.y, h0, l0); split2(v.z, v.w, h1, l1);
            *(uint32_t*)(sWh + wr * ELD + k)     = h0;
            *(uint32_t*)(sWh + wr * ELD + k + 2) = h1;
            *(uint32_t*)(sWl + wr * ELD + k)     = l0;
            *(uint32_t*)(sWl + wr * ELD + k + 2) = l1;
        }
    }
    __syncthreads();

    wmma::fragment<wmma::matrix_a, 16, 16, 16, bf16, wmma::row_major> ah[4], al[4];
    wmma::fragment<wmma::matrix_b, 16, 16, 16, bf16, wmma::col_major> bh, bl;
    #pragma unroll
    for (int ks = 0; ks < 4; ks++) {
        wmma::load_matrix_sync(ah[ks], sAh + wid * 16 * ELD + ks * 16, ELD);
        wmma::load_matrix_sync(al[ks], sAl + wid * 16 * ELD + ks * 16, ELD);
    }
    __syncthreads();   // A region now per-warp staging

    float* stg = (float*)(smem + wid * (16 * SLD * 4));
    const int er0 = e0 + wid * 16;
    const int c2 = lane * 2;

    #pragma unroll 1
    for (int chunk = 0; chunk < 4; chunk++) {
        const int c = chunk * 64 + c2;
        // prefetch pn batch 0 (edges 0-7) — consumed after MMA
        uint32_t pn0[8];
        #pragma unroll
        for (int j = 0; j < 8; j++)
            pn0[j] = *(const uint32_t*)(g_Pnbrh + (size_t)sIdx[wid * 16 + j] * CDIM + c);

        wmma::fragment<wmma::accumulator, 16, 16, 16, float> acc[4];
        #pragma unroll
        for (int nt = 0; nt < 4; nt++) wmma::fill_fragment(acc[nt], 0.f);
        #pragma unroll
        for (int ks = 0; ks < 4; ks++) {
            #pragma unroll
            for (int nt = 0; nt < 4; nt++) {
                const int nc = (chunk * 64 + nt * 16) * ELD + ks * 16;
                wmma::load_matrix_sync(bh, sWh + nc, ELD);
                wmma::load_matrix_sync(bl, sWl + nc, ELD);
                wmma::mma_sync(acc[nt], ah[ks], bh, acc[nt]);
                wmma::mma_sync(acc[nt], ah[ks], bl, acc[nt]);
                wmma::mma_sync(acc[nt], al[ks], bh, acc[nt]);
            }
        }
        #pragma unroll
        for (int nt = 0; nt < 4; nt++)
            wmma::store_matrix_sync(stg + nt * 16, acc[nt], SLD, wmma::mem_row_major);
        __syncwarp();

        // prefetch pn batch 1 (edges 8-15)
        uint32_t pn1[8];
        #pragma unroll
        for (int j = 0; j < 8; j++)
            pn1[j] = *(const uint32_t*)(g_Pnbrh + (size_t)sIdx[wid * 16 + 8 + j] * CDIM + c);

        const float bc0 = sB[c], bc1 = sB[c + 1];
        float s0 = 0.f, q0 = 0.f, s1 = 0.f, q1 = 0.f;
        #pragma unroll
        for (int j = 0; j < 16; j++) {
            int e = er0 + j;
            int a = e / MNBR; if (a >= N) a = N - 1;
            float2 ps = *(const float2*)(g_Pself + (size_t)a * CDIM + c);
            uint32_t pnu = (j < 8) ? pn0[j] : pn1[j - 8];
            float2 pn = __half22float2(*(__half2*)&pnu);
            float v0 = stg[j * SLD + c2]     + pn.x + ps.x + bc0;
            float v1 = stg[j * SLD + c2 + 1] + pn.y + ps.y + bc1;
            __half2 h2 = __floats2half2_rn(v0, v1);
            if (e < Ntot) {
                *(__half2*)(g_gatedh + (size_t)e * CDIM + c) = h2;
                float2 f = __half22float2(h2);
                s0 += f.x; q0 += f.x * f.x; s1 += f.y; q1 += f.y * f.y;
            }
        }
        atomicAdd(&g_sum1[c], s0);     atomicAdd(&g_sq1[c], q0);
        atomicAdd(&g_sum1[c + 1], s1); atomicAdd(&g_sq1[c + 1], q1);
        __syncwarp();
    }
}

__global__ void k_fin1(const float* __restrict__ gm, const float* __restrict__ bt, float ic) {
    int c = threadIdx.x;
    float mean = g_sum1[c] * ic, var = g_sq1[c] * ic - mean * mean;
    float sc = gm[c] * rsqrtf(var + 1e-5f);
    g_scale1[c] = sc; g_shift1[c] = bt[c] - mean * sc;
}

// ---- K3: gate + neighbor sum via smem staging (coalesced). 8 atoms/block. ---
__global__ void __launch_bounds__(256) k_sum(int N, int Ntot) {
    __shared__ __align__(16) __half sg[96 * 256];   // 48 KB
    const int tid = threadIdx.x;
    const int n0 = blockIdx.x * 8;
    const size_t e0 = (size_t)n0 * MNBR;
    const uint4* src = (const uint4*)(g_gatedh + e0 * CDIM);
    #pragma unroll
    for (int it = 0; it < 12; it++) {
        int i = it * 256 + tid;                      // uint4 index; 32 per edge row
        if (e0 + (size_t)(i >> 5) < (size_t)Ntot) ((uint4*)sg)[i] = src[i];
    }
    __syncthreads();

    const int p = tid & 63, grp = tid >> 6;
    const __half2* sg2 = (const __half2*)sg;
    const float scf0 = g_scale1[2 * p],           shf0 = g_shift1[2 * p];
    const float scf1 = g_scale1[2 * p + 1],       shf1 = g_shift1[2 * p + 1];
    const float scc0 = g_scale1[128 + 2 * p],     shc0 = g_shift1[128 + 2 * p];
    const float scc1 = g_scale1[128 + 2 * p + 1], shc1 = g_shift1[128 + 2 * p + 1];
    float ls0 = 0.f, lq0 = 0.f, ls1 = 0.f, lq1 = 0.f;
    #pragma unroll
    for (int ai = 0; ai < 2; ai++) {
        const int a = grp * 2 + ai, n = n0 + a;
        if (n >= N) break;
        float a0 = 0.f, a1 = 0.f;
        #pragma unroll
        for (int m = 0; m < MNBR; m++) {
            int base = (a * MNBR + m) * 128;
            float2 hf = __half22float2(sg2[base + p]);
            float2 hc = __half22float2(sg2[base + 64 + p]);
            float gf0 = hf.x * scf0 + shf0, gf1 = hf.y * scf1 + shf1;
            float gc0 = hc.x * scc0 + shc0, gc1 = hc.y * scc1 + shc1;
            a0 += (1.f / (1.f + expf(-gf0))) * (gc0 > 0.f ? gc0 : 0.f);
            a1 += (1.f / (1.f + expf(-gf1))) * (gc1 > 0.f ? gc1 : 0.f);
        }
        *(float2*)(g_nbrsum + (size_t)n * FDIM + 2 * p) = make_float2(a0, a1);
        ls0 += a0; lq0 += a0 * a0; ls1 += a1; lq1 += a1 * a1;
    }
    atomicAdd(&g_sum2[2 * p], ls0);     atomicAdd(&g_sq2[2 * p], lq0);
    atomicAdd(&g_sum2[2 * p + 1], ls1); atomicAdd(&g_sq2[2 * p + 1], lq1);
}

__global__ void k_fin2(const float* __restrict__ gm, const float* __restrict__ bt, float ic) {
    int c = threadIdx.x;
    float mean = g_sum2[c] * ic, var = g_sq2[c] * ic - mean * mean;
    float sc = gm[c] * rsqrtf(var + 1e-5f);
    g_scale2[c] = sc; g_shift2[c] = bt[c] - mean * sc;
}
__global__ void k_out(const float* __restrict__ atom, float* __restrict__ out, int total) {
    int i = blockIdx.x * blockDim.x + threadIdx.x;
    if (i < total) {
        int f = i & 127;
        float v = atom[i] + g_nbrsum[i] * g_scale2[f] + g_shift2[f];
        out[i] = v > 0.f ? v : 0.f;
    }
}

extern "C" void kernel_launch(void* const* d_in, const int* in_sizes, int n_in,
                              void* d_out, int out_size) {
    const float* atom = (const float*)d_in[0];
    const float* nbr  = (const float*)d_in[1];
    const void*  idx  = d_in[2];
    const float* W    = (const float*)d_in[3];
    const float* b    = (const float*)d_in[4];
    const float* g1   = (const float*)d_in[5];
    const float* b1   = (const float*)d_in[6];
    const float* g2   = (const float*)d_in[7];
    const float* b2   = (const float*)d_in[8];
    float* out = (float*)d_out;
    const int N = in_sizes[0] / FDIM;
    const int Ntot = N * MNBR;

    const int smP = (2 * 128 * PLD + 2 * 256 * PLD) * 2;   // 208896
    static int configured = 0;
    if (!configured) {
        cudaFuncSetAttribute(k_proj, cudaFuncAttributeMaxDynamicSharedMemorySize, smP);
        cudaFuncSetAttribute(k_edge, cudaFuncAttributeMaxDynamicSharedMemorySize, SME);
        configured = 1;
    }

    k_init<<<(Ntot + 255) / 256, 256>>>(idx, Ntot);                // 1
    dim3 gp((N + 127) / 128, 2);
    k_proj<<<gp, 512, smP>>>(atom, W, N);                          // 2
    k_cvt<<<(N * CDIM / 4 + 255) / 256, 256>>>(N * CDIM / 4);      // 3
    k_edge<<<(Ntot + 255) / 256, 512, SME>>>(nbr, W, b, N, Ntot);  // 4 <- ncu slot
    k_fin1<<<1, CDIM>>>(g1, b1, 1.f / ((float)N * (float)MNBR));   // 5
    k_sum<<<(N + 7) / 8, 256>>>(N, Ntot);                          // 6
    k_fin2<<<1, FDIM>>>(g2, b2, 1.f / (float)N);                   // 7
    k_out<<<((size_t)N * FDIM + 255) / 256, 256>>>(atom, out, N * FDIM);
}

// round 15
// speedup vs baseline: 1.1454x; 1.1454x over previous
#include <cuda_runtime.h>
#include <cuda_bf16.h>
#include <cuda_fp16.h>
#include <mma.h>
#include <cstdint>
#include <cstddef>

using namespace nvcuda;

#define FDIM 128
#define KDIM 64
#define CDIM 256
#define MNBR 12
#define NMAX 100000
#define NEDGE (NMAX * MNBR)

typedef __nv_bfloat16 bf16;

__device__ bf16   g_Ah[(size_t)NEDGE * KDIM];    // edge features hi, frag-ready
__device__ bf16   g_Al[(size_t)NEDGE * KDIM];    // edge features lo
__device__ bf16   g_Wh3[256 * KDIM];             // W3 hi  [ch][k]
__device__ bf16   g_Wl3[256 * KDIM];             // W3 lo
__device__ __half g_Pselfh[(size_t)NMAX * CDIM];
__device__ __half g_Pnbrh [(size_t)NMAX * CDIM];
__device__ __half g_gatedh[(size_t)NEDGE * CDIM];
__device__ float  g_nbrsum[(size_t)NMAX * FDIM];
__device__ int    g_idx32[NEDGE];
__device__ float  g_sum1[CDIM], g_sq1[CDIM], g_scale1[CDIM], g_shift1[CDIM];
__device__ float  g_sum2[FDIM], g_sq2[FDIM], g_scale2[FDIM], g_shift2[FDIM];

__device__ __forceinline__ void split2(float a, float b, uint32_t& hi, uint32_t& lo) {
    __nv_bfloat162 H, L;
    H.x = __float2bfloat16(a); H.y = __float2bfloat16(b);
    L.x = __float2bfloat16(a - __bfloat162float(H.x));
    L.y = __float2bfloat16(b - __bfloat162float(H.y));
    hi = *(uint32_t*)&H; lo = *(uint32_t*)&L;
}

// ---- K0: zero stats + normalize indices (per-block dtype detect) ------------
__global__ void k_init(const void* __restrict__ raw, int total) {
    __shared__ int s64;
    const int tid = threadIdx.x;
    if (tid == 0) {
        const int* w = (const int*)raw;
        int nz = 0;
        #pragma unroll 4
        for (int i = 1; i < 128; i += 2) nz |= (w[i] != 0);
        s64 = nz ? 0 : 1;
    }
    __syncthreads();
    int i = blockIdx.x * blockDim.x + tid;
    if (i < total)
        g_idx32[i] = s64 ? (int)((const long long*)raw)[i] : ((const int*)raw)[i];
    if (blockIdx.x == 0) {
        if (tid < CDIM) { g_sum1[tid] = 0.f; g_sq1[tid] = 0.f; }
        if (tid < FDIM) { g_sum2[tid] = 0.f; g_sq2[tid] = 0.f; }
    }
}

// ---- K0b: split edge features + W3 to bf16 hi/lo gmem buffers ---------------
__global__ void k_prep(const float* __restrict__ nbr, const float* __restrict__ W,
                       int na4) {
    int i = blockIdx.x * blockDim.x + threadIdx.x;
    if (i < na4) {
        float4 v = ((const float4*)nbr)[i];
        uint2 uh, ul;
        split2(v.x, v.y, uh.x, ul.x); split2(v.z, v.w, uh.y, ul.y);
        ((uint2*)g_Ah)[i] = uh; ((uint2*)g_Al)[i] = ul;
    } else {
        int j = i - na4;                       // float4 index into [256][64] W3
        if (j < 256 * KDIM / 4) {
            int ch = j >> 4, k = (j & 15) * 4;
            float4 v = *(const float4*)(W + (size_t)ch * 320 + 256 + k);
            uint2 uh, ul;
            split2(v.x, v.y, uh.x, ul.x); split2(v.z, v.w, uh.y, ul.y);
            ((uint2*)g_Wh3)[j] = uh; ((uint2*)g_Wl3)[j] = ul;
        }
    }
}

// ---- K1: projection GEMMs -> fp16 P tables. grid (ceil(N/128), 2). ----------
#define PLD 136
#define OSTG 208896
__global__ void __launch_bounds__(512) k_proj(const float* __restrict__ atom,
                                              const float* __restrict__ W, int N) {
    extern __shared__ __align__(16) char smem[];
    bf16* sAh = (bf16*)smem;
    bf16* sAl = sAh + 128 * PLD;
    bf16* sWh = sAl + 128 * PLD;
    bf16* sWl = sWh + 256 * PLD;
    const int tid = threadIdx.x, wid = tid >> 5, lane = tid & 31;
    const int part = blockIdx.y, n0 = blockIdx.x * 128;

    {   // A: row = tid/4, quarter = tid&3
        int row = tid >> 2, q = tid & 3, n = n0 + row;
        #pragma unroll
        for (int i = 0; i < 8; i++) {
            float4 v = (n < N) ? *(const float4*)(atom + (size_t)n * FDIM + q * 32 + i * 4)
                               : make_float4(0.f, 0.f, 0.f, 0.f);
            int k = q * 32 + i * 4;
            uint32_t h0, l0, h1, l1;
            split2(v.x, v.y, h0, l0); split2(v.z, v.w, h1, l1);
            *(uint32_t*)(sAh + row * PLD + k)     = h0;
            *(uint32_t*)(sAh + row * PLD + k + 2) = h1;
            *(uint32_t*)(sAl + row * PLD + k)     = l0;
            *(uint32_t*)(sAl + row * PLD + k + 2) = l1;
        }
    }
    {   // W: row = tid/2, half = tid&1
        int wr = tid >> 1, hf = tid & 1;
        const float* wp = W + (size_t)wr * 320 + part * 128 + hf * 64;
        #pragma unroll
        for (int i = 0; i < 16; i++) {
            float4 v = *(const float4*)(wp + i * 4);
            int k = hf * 64 + i * 4;
            uint32_t h0, l0, h1, l1;
            split2(v.x, v.y, h0, l0); split2(v.z, v.w, h1, l1);
            *(uint32_t*)(sWh + wr * PLD + k)     = h0;
            *(uint32_t*)(sWh + wr * PLD + k + 2) = h1;
            *(uint32_t*)(sWl + wr * PLD + k)     = l0;
            *(uint32_t*)(sWl + wr * PLD + k + 2) = l1;
        }
    }
    __syncthreads();

    const int atile = wid >> 1, nh = wid & 1;
    const int nbase = n0 + atile * 16;
    if (nbase >= N) return;
    __half* outh = (part ? g_Pnbrh : g_Pselfh) + (size_t)nbase * CDIM + nh * 128;
    float* wstg = (float*)(smem + OSTG) + wid * 320;   // 16 x 20 per warp

    wmma::fragment<wmma::matrix_a, 16, 16, 16, bf16, wmma::row_major> ah[8], al;
    wmma::fragment<wmma::matrix_b, 16, 16, 16, bf16, wmma::col_major> bh, bl;
    wmma::fragment<wmma::accumulator, 16, 16, 16, float> acc;
    #pragma unroll
    for (int ks = 0; ks < 8; ks++)
        wmma::load_matrix_sync(ah[ks], sAh + atile * 16 * PLD + ks * 16, PLD);
    const int orow = lane >> 1, ocb = (lane & 1) * 8;
    #pragma unroll 1
    for (int nt = 0; nt < 8; nt++) {
        wmma::fill_fragment(acc, 0.f);
        #pragma unroll
        for (int ks = 0; ks < 8; ks++) {
            const int nc = (nh * 128 + nt * 16) * PLD + ks * 16;
            wmma::load_matrix_sync(bh, sWh + nc, PLD);
            wmma::load_matrix_sync(bl, sWl + nc, PLD);
            wmma::load_matrix_sync(al, sAl + atile * 16 * PLD + ks * 16, PLD);
            wmma::mma_sync(acc, ah[ks], bh, acc);
            wmma::mma_sync(acc, ah[ks], bl, acc);
            wmma::mma_sync(acc, al, bh, acc);
        }
        wmma::store_matrix_sync(wstg, acc, 20, wmma::mem_row_major);
        __syncwarp();
        if (nbase + orow < N) {
            __half2 h[4];
            #pragma unroll
            for (int q = 0; q < 4; q++)
                h[q] = __floats2half2_rn(wstg[orow * 20 + ocb + 2 * q],
                                         wstg[orow * 20 + ocb + 2 * q + 1]);
            *(uint4*)(outh + (size_t)orow * CDIM + nt * 16 + ocb) = *(uint4*)h;
        }
        __syncwarp();
    }
}

// ---- K2: edge GEMM from gmem fragments + gathers + gated + BN1 stats. -------
// grid ceil(Ntot/128), 256 thr (8 warps x 16 edges). No A/W smem, no conversion.
#define SLD 68
__global__ void __launch_bounds__(256) k_edge(const float* __restrict__ bias,
                                              int N, int Ntot) {
    __shared__ float stg[8][16 * SLD];   // 34.8 KB
    __shared__ float sB[256];
    __shared__ int   sIdx[128];
    const int tid = threadIdx.x, wid = tid >> 5, lane = tid & 31;
    const int e0 = blockIdx.x * 128;
    const int er0 = e0 + wid * 16;

    if (tid < 128) sIdx[tid] = (e0 + tid < Ntot) ? g_idx32[e0 + tid] : 0;
    sB[tid] = bias[tid];
    __syncthreads();

    wmma::fragment<wmma::matrix_a, 16, 16, 16, bf16, wmma::row_major> ah[4], al;
    wmma::fragment<wmma::matrix_b, 16, 16, 16, bf16, wmma::col_major> bh, bl;
    #pragma unroll
    for (int ks = 0; ks < 4; ks++)
        wmma::load_matrix_sync(ah[ks], g_Ah + (size_t)er0 * KDIM + ks * 16, KDIM);

    const int c2 = lane * 2;
    float* ws = stg[wid];

    #pragma unroll 1
    for (int chunk = 0; chunk < 4; chunk++) {
        const int c = chunk * 64 + c2;
        // prefetch gathers for edges 0-7 (consumed after MMA)
        uint32_t pn0[8], ps0[8];
        #pragma unroll
        for (int j = 0; j < 8; j++) {
            pn0[j] = *(const uint32_t*)(g_Pnbrh + (size_t)sIdx[wid * 16 + j] * CDIM + c);
            int a = (er0 + j) / MNBR; if (a >= N) a = N - 1;
            ps0[j] = *(const uint32_t*)(g_Pselfh + (size_t)a * CDIM + c);
        }

        wmma::fragment<wmma::accumulator, 16, 16, 16, float> acc[4];
        #pragma unroll
        for (int nt = 0; nt < 4; nt++) wmma::fill_fragment(acc[nt], 0.f);
        #pragma unroll
        for (int ks = 0; ks < 4; ks++) {
            wmma::load_matrix_sync(al, g_Al + (size_t)er0 * KDIM + ks * 16, KDIM);
            #pragma unroll
            for (int nt = 0; nt < 4; nt++) {
                const int c0 = chunk * 64 + nt * 16;
                wmma::load_matrix_sync(bh, g_Wh3 + c0 * KDIM + ks * 16, KDIM);
                wmma::load_matrix_sync(bl, g_Wl3 + c0 * KDIM + ks * 16, KDIM);
                wmma::mma_sync(acc[nt], ah[ks], bh, acc[nt]);
                wmma::mma_sync(acc[nt], ah[ks], bl, acc[nt]);
                wmma::mma_sync(acc[nt], al, bh, acc[nt]);
            }
        }
        #pragma unroll
        for (int nt = 0; nt < 4; nt++)
            wmma::store_matrix_sync(ws + nt * 16, acc[nt], SLD, wmma::mem_row_major);
        __syncwarp();

        // prefetch gathers for edges 8-15
        uint32_t pn1[8], ps1[8];
        #pragma unroll
        for (int j = 0; j < 8; j++) {
            pn1[j] = *(const uint32_t*)(g_Pnbrh + (size_t)sIdx[wid * 16 + 8 + j] * CDIM + c);
            int a = (er0 + 8 + j) / MNBR; if (a >= N) a = N - 1;
            ps1[j] = *(const uint32_t*)(g_Pselfh + (size_t)a * CDIM + c);
        }

        const float bc0 = sB[c], bc1 = sB[c + 1];
        float s0 = 0.f, q0 = 0.f, s1 = 0.f, q1 = 0.f;
        #pragma unroll
        for (int j = 0; j < 16; j++) {
            int e = er0 + j;
            uint32_t pnu = (j < 8) ? pn0[j] : pn1[j - 8];
            uint32_t psu = (j < 8) ? ps0[j] : ps1[j - 8];
            float2 pn = __half22float2(*(__half2*)&pnu);
            float2 ps = __half22float2(*(__half2*)&psu);
            float v0 = ws[j * SLD + c2]     + pn.x + ps.x + bc0;
            float v1 = ws[j * SLD + c2 + 1] + pn.y + ps.y + bc1;
            __half2 h2 = __floats2half2_rn(v0, v1);
            if (e < Ntot) {
                *(__half2*)(g_gatedh + (size_t)e * CDIM + c) = h2;
                float2 f = __half22float2(h2);
                s0 += f.x; q0 += f.x * f.x; s1 += f.y; q1 += f.y * f.y;
            }
        }
        atomicAdd(&g_sum1[c], s0);     atomicAdd(&g_sq1[c], q0);
        atomicAdd(&g_sum1[c + 1], s1); atomicAdd(&g_sq1[c + 1], q1);
        __syncwarp();
    }
}

__global__ void k_fin1(const float* __restrict__ gm, const float* __restrict__ bt, float ic) {
    int c = threadIdx.x;
    float mean = g_sum1[c] * ic, var = g_sq1[c] * ic - mean * mean;
    float sc = gm[c] * rsqrtf(var + 1e-5f);
    g_scale1[c] = sc; g_shift1[c] = bt[c] - mean * sc;
}

// ---- K3: gate + neighbor sum (R12 version) ----------------------------------
__global__ void __launch_bounds__(256) k_sum(int N) {
    const int p = threadIdx.x & 63, g = threadIdx.x >> 6, n0 = blockIdx.x * 32;
    const float scf0 = g_scale1[2 * p], shf0 = g_shift1[2 * p];
    const float scf1 = g_scale1[2 * p + 1], shf1 = g_shift1[2 * p + 1];
    const float scc0 = g_scale1[128 + 2 * p], shc0 = g_shift1[128 + 2 * p];
    const float scc1 = g_scale1[128 + 2 * p + 1], shc1 = g_shift1[128 + 2 * p + 1];
    float ls0 = 0.f, lq0 = 0.f, ls1 = 0.f, lq1 = 0.f;
    for (int a = g; a < 32; a += 4) {
        const int n = n0 + a;
        if (n >= N) break;
        const __half* row = g_gatedh + (size_t)n * MNBR * CDIM;
        float a0 = 0.f, a1 = 0.f;
        #pragma unroll
        for (int m = 0; m < MNBR; m++) {
            float2 hf = __half22float2(*(const __half2*)(row + (size_t)m * CDIM + 2 * p));
            float2 hc = __half22float2(*(const __half2*)(row + (size_t)m * CDIM + 128 + 2 * p));
            float gf0 = hf.x * scf0 + shf0, gf1 = hf.y * scf1 + shf1;
            float gc0 = hc.x * scc0 + shc0, gc1 = hc.y * scc1 + shc1;
            a0 += (1.f / (1.f + expf(-gf0))) * (gc0 > 0.f ? gc0 : 0.f);
            a1 += (1.f / (1.f + expf(-gf1))) * (gc1 > 0.f ? gc1 : 0.f);
        }
        *(float2*)(g_nbrsum + (size_t)n * FDIM + 2 * p) = make_float2(a0, a1);
        ls0 += a0; lq0 += a0 * a0; ls1 += a1; lq1 += a1 * a1;
    }
    atomicAdd(&g_sum2[2 * p], ls0);     atomicAdd(&g_sq2[2 * p], lq0);
    atomicAdd(&g_sum2[2 * p + 1], ls1); atomicAdd(&g_sq2[2 * p + 1], lq1);
}
__global__ void k_fin2(const float* __restrict__ gm, const float* __restrict__ bt, float ic) {
    int c = threadIdx.x;
    float mean = g_sum2[c] * ic, var = g_sq2[c] * ic - mean * mean;
    float sc = gm[c] * rsqrtf(var + 1e-5f);
    g_scale2[c] = sc; g_shift2[c] = bt[c] - mean * sc;
}
__global__ void k_out(const float* __restrict__ atom, float* __restrict__ out, int total) {
    int i = blockIdx.x * blockDim.x + threadIdx.x;
    if (i < total) {
        int f = i & 127;
        float v = atom[i] + g_nbrsum[i] * g_scale2[f] + g_shift2[f];
        out[i] = v > 0.f ? v : 0.f;
    }
}

extern "C" void kernel_launch(void* const* d_in, const int* in_sizes, int n_in,
                              void* d_out, int out_size) {
    const float* atom = (const float*)d_in[0];
    const float* nbr  = (const float*)d_in[1];
    const void*  idx  = d_in[2];
    const float* W    = (const float*)d_in[3];
    const float* b    = (const float*)d_in[4];
    const float* g1   = (const float*)d_in[5];
    const float* b1   = (const float*)d_in[6];
    const float* g2   = (const float*)d_in[7];
    const float* b2   = (const float*)d_in[8];
    float* out = (float*)d_out;
    const int N = in_sizes[0] / FDIM;
    const int Ntot = N * MNBR;
    const int na4 = Ntot * (KDIM / 4);

    const int smP = OSTG + 16 * 320 * 4;   // 229376
    static int configured = 0;
    if (!configured) {
        cudaFuncSetAttribute(k_proj, cudaFuncAttributeMaxDynamicSharedMemorySize, smP);
        configured = 1;
    }

    k_init<<<(Ntot + 255) / 256, 256>>>(idx, Ntot);                  // 1
    k_prep<<<(na4 + 4096 + 255) / 256, 256>>>(nbr, W, na4);          // 2
    dim3 gp((N + 127) / 128, 2);
    k_proj<<<gp, 512, smP>>>(atom, W, N);                            // 3
    k_edge<<<(Ntot + 127) / 128, 256>>>(b, N, Ntot);                 // 4 <- ncu slot
    k_fin1<<<1, CDIM>>>(g1, b1, 1.f / ((float)N * (float)MNBR));     // 5
    k_sum<<<(N + 31) / 32, 256>>>(N);                                // 6
    k_fin2<<<1, FDIM>>>(g2, b2, 1.f / (float)N);                     // 7
    k_out<<<((size_t)N * FDIM + 255) / 256, 256>>>(atom, out, N * FDIM);
}

// round 16
// speedup vs baseline: 1.2449x; 1.0869x over previous
#include <cuda_runtime.h>
#include <cuda_bf16.h>
#include <cuda_fp16.h>
#include <mma.h>
#include <cstdint>
#include <cstddef>

using namespace nvcuda;

#define FDIM 128
#define KDIM 64
#define CDIM 256
#define MNBR 12
#define NMAX 100000
#define NEDGE (NMAX * MNBR)

typedef __nv_bfloat16 bf16;

// packed fragment buffers (b32 granularity)
__device__ uint32_t g_Ahp[(size_t)NEDGE * 32];   // A hi: [tile16][kt4][lane32][4]
__device__ uint32_t g_Alp[(size_t)NEDGE * 32];   // A lo
__device__ uint32_t g_Whp[8192];                 // W3 hi: [ct32][kt4][lane32][2]
__device__ uint32_t g_Wlp[8192];                 // W3 lo
__device__ __half g_Pselfh[(size_t)NMAX * CDIM];
__device__ __half g_Pnbrh [(size_t)NMAX * CDIM];
__device__ __half g_gatedh[(size_t)NEDGE * CDIM];
__device__ float  g_nbrsum[(size_t)NMAX * FDIM];
__device__ int    g_idx32[NEDGE];
__device__ float  g_sum1[CDIM], g_sq1[CDIM], g_scale1[CDIM], g_shift1[CDIM];
__device__ float  g_sum2[FDIM], g_sq2[FDIM], g_scale2[FDIM], g_shift2[FDIM];

__device__ __forceinline__ void split2(float a, float b, uint32_t& hi, uint32_t& lo) {
    __nv_bfloat162 H, L;
    H.x = __float2bfloat16(a); H.y = __float2bfloat16(b);
    L.x = __float2bfloat16(a - __bfloat162float(H.x));
    L.y = __float2bfloat16(b - __bfloat162float(H.y));
    hi = *(uint32_t*)&H; lo = *(uint32_t*)&L;
}
__device__ __forceinline__ void mma16816(float* d, const uint4& a, const uint2& b) {
    asm volatile("mma.sync.aligned.m16n8k16.row.col.f32.bf16.bf16.f32 "
        "{%0,%1,%2,%3}, {%4,%5,%6,%7}, {%8,%9}, {%0,%1,%2,%3};"
        : "+f"(d[0]), "+f"(d[1]), "+f"(d[2]), "+f"(d[3])
        : "r"(a.x), "r"(a.y), "r"(a.z), "r"(a.w), "r"(b.x), "r"(b.y));
}

// ---- K0: zero stats + normalize indices (per-block dtype detect) ------------
__global__ void k_init(const void* __restrict__ raw, int total) {
    __shared__ int s64;
    const int tid = threadIdx.x;
    if (tid == 0) {
        const int* w = (const int*)raw;
        int nz = 0;
        #pragma unroll 4
        for (int i = 1; i < 128; i += 2) nz |= (w[i] != 0);
        s64 = nz ? 0 : 1;
    }
    __syncthreads();
    int i = blockIdx.x * blockDim.x + tid;
    if (i < total)
        g_idx32[i] = s64 ? (int)((const long long*)raw)[i] : ((const int*)raw)[i];
    if (blockIdx.x == 0) {
        if (tid < CDIM) { g_sum1[tid] = 0.f; g_sq1[tid] = 0.f; }
        if (tid < FDIM) { g_sum2[tid] = 0.f; g_sq2[tid] = 0.f; }
    }
}

// ---- K0b: pack edge features + W3 into m16n8k16 fragment layouts ------------
// A (16x16 row-major): reg j: row = (lane>>2) + (j&1)*8, k = (lane&3)*2 + (j>>1)*8
// B (16x8 col):        reg j: ch  = nt*8 + (lane>>2),    k = (lane&3)*2 + j*8
__global__ void k_prep(const float* __restrict__ nbr, const float* __restrict__ W,
                       int nA, int Ntot) {
    int i = blockIdx.x * blockDim.x + threadIdx.x;
    if (i < nA) {                       // A: i = (T*4 + kt)*32 + lane
        int lane = i & 31, kt = (i >> 5) & 3, T = i >> 7;
        int r0 = lane >> 2, tig = lane & 3;
        uint32_t h[4], l[4];
        #pragma unroll
        for (int j = 0; j < 4; j++) {
            int e = T * 16 + r0 + (j & 1) * 8;
            int kk = kt * 16 + tig * 2 + (j >> 1) * 8;
            float2 v = (e < Ntot) ? *(const float2*)(nbr + (size_t)e * KDIM + kk)
                                  : make_float2(0.f, 0.f);
            split2(v.x, v.y, h[j], l[j]);
        }
        *(uint4*)(g_Ahp + (size_t)i * 4) = make_uint4(h[0], h[1], h[2], h[3]);
        *(uint4*)(g_Alp + (size_t)i * 4) = make_uint4(l[0], l[1], l[2], l[3]);
    } else {
        int q = i - nA;                 // W: q = (ct*4 + kt)*32 + lane
        if (q < 4096) {
            int lane = q & 31, kt = (q >> 5) & 3, ct = q >> 7;
            int ch = ct * 8 + (lane >> 2), tig = lane & 3;
            uint32_t h[2], l[2];
            #pragma unroll
            for (int j = 0; j < 2; j++) {
                int kk = kt * 16 + tig * 2 + j * 8;
                float2 v = *(const float2*)(W + (size_t)ch * 320 + 256 + kk);
                split2(v.x, v.y, h[j], l[j]);
            }
            *(uint2*)(g_Whp + (size_t)q * 2) = make_uint2(h[0], h[1]);
            *(uint2*)(g_Wlp + (size_t)q * 2) = make_uint2(l[0], l[1]);
        }
    }
}

// ---- K1: projection GEMMs -> fp16 P tables (unchanged, known-good) ----------
#define PLD 136
#define OSTG 208896
__global__ void __launch_bounds__(512) k_proj(const float* __restrict__ atom,
                                              const float* __restrict__ W, int N) {
    extern __shared__ __align__(16) char smem[];
    bf16* sAh = (bf16*)smem;
    bf16* sAl = sAh + 128 * PLD;
    bf16* sWh = sAl + 128 * PLD;
    bf16* sWl = sWh + 256 * PLD;
    const int tid = threadIdx.x, wid = tid >> 5, lane = tid & 31;
    const int part = blockIdx.y, n0 = blockIdx.x * 128;

    {   int row = tid >> 2, q = tid & 3, n = n0 + row;
        #pragma unroll
        for (int i = 0; i < 8; i++) {
            float4 v = (n < N) ? *(const float4*)(atom + (size_t)n * FDIM + q * 32 + i * 4)
                               : make_float4(0.f, 0.f, 0.f, 0.f);
            int k = q * 32 + i * 4;
            uint32_t h0, l0, h1, l1;
            split2(v.x, v.y, h0, l0); split2(v.z, v.w, h1, l1);
            *(uint32_t*)(sAh + row * PLD + k)     = h0;
            *(uint32_t*)(sAh + row * PLD + k + 2) = h1;
            *(uint32_t*)(sAl + row * PLD + k)     = l0;
            *(uint32_t*)(sAl + row * PLD + k + 2) = l1;
        }
    }
    {   int wr = tid >> 1, hf = tid & 1;
        const float* wp = W + (size_t)wr * 320 + part * 128 + hf * 64;
        #pragma unroll
        for (int i = 0; i < 16; i++) {
            float4 v = *(const float4*)(wp + i * 4);
            int k = hf * 64 + i * 4;
            uint32_t h0, l0, h1, l1;
            split2(v.x, v.y, h0, l0); split2(v.z, v.w, h1, l1);
            *(uint32_t*)(sWh + wr * PLD + k)     = h0;
            *(uint32_t*)(sWh + wr * PLD + k + 2) = h1;
            *(uint32_t*)(sWl + wr * PLD + k)     = l0;
            *(uint32_t*)(sWl + wr * PLD + k + 2) = l1;
        }
    }
    __syncthreads();

    const int atile = wid >> 1, nh = wid & 1;
    const int nbase = n0 + atile * 16;
    if (nbase >= N) return;
    __half* outh = (part ? g_Pnbrh : g_Pselfh) + (size_t)nbase * CDIM + nh * 128;
    float* wstg = (float*)(smem + OSTG) + wid * 320;

    wmma::fragment<wmma::matrix_a, 16, 16, 16, bf16, wmma::row_major> ah[8], al;
    wmma::fragment<wmma::matrix_b, 16, 16, 16, bf16, wmma::col_major> bh, bl;
    wmma::fragment<wmma::accumulator, 16, 16, 16, float> acc;
    #pragma unroll
    for (int ks = 0; ks < 8; ks++)
        wmma::load_matrix_sync(ah[ks], sAh + atile * 16 * PLD + ks * 16, PLD);
    const int orow = lane >> 1, ocb = (lane & 1) * 8;
    #pragma unroll 1
    for (int nt = 0; nt < 8; nt++) {
        wmma::fill_fragment(acc, 0.f);
        #pragma unroll
        for (int ks = 0; ks < 8; ks++) {
            const int nc = (nh * 128 + nt * 16) * PLD + ks * 16;
            wmma::load_matrix_sync(bh, sWh + nc, PLD);
            wmma::load_matrix_sync(bl, sWl + nc, PLD);
            wmma::load_matrix_sync(al, sAl + atile * 16 * PLD + ks * 16, PLD);
            wmma::mma_sync(acc, ah[ks], bh, acc);
            wmma::mma_sync(acc, ah[ks], bl, acc);
            wmma::mma_sync(acc, al, bh, acc);
        }
        wmma::store_matrix_sync(wstg, acc, 20, wmma::mem_row_major);
        __syncwarp();
        if (nbase + orow < N) {
            __half2 h[4];
            #pragma unroll
            for (int q = 0; q < 4; q++)
                h[q] = __floats2half2_rn(wstg[orow * 20 + ocb + 2 * q],
                                         wstg[orow * 20 + ocb + 2 * q + 1]);
            *(uint4*)(outh + (size_t)orow * CDIM + nt * 16 + ocb) = *(uint4*)h;
        }
        __syncwarp();
    }
}

// ---- K2: edge GEMM (raw mma, packed frags) + gathers + gated + BN1 stats ----
// 128 thr (4 warps x 16 edges), grid ceil(Ntot/64). No A/W smem, no conversion.
#define SLD 68
__global__ void __launch_bounds__(128, 4) k_edge(const float* __restrict__ bias,
                                                 int N, int Ntot) {
    __shared__ float stg[4][16 * SLD];   // 17.4 KB
    __shared__ float sB[256];
    __shared__ int   sIdx[64];
    const int tid = threadIdx.x, wid = tid >> 5, lane = tid & 31;
    const int e0 = blockIdx.x * 64;
    const int er0 = e0 + wid * 16;
    const int T = blockIdx.x * 4 + wid;            // A tile index

    if (tid < 64) sIdx[tid] = (e0 + tid < Ntot) ? g_idx32[e0 + tid] : 0;
    sB[tid] = bias[tid]; sB[tid + 128] = bias[tid + 128];
    __syncthreads();

    // A fragments: coalesced LDG.128, frag-packed
    uint4 ah4[4], al4[4];
    #pragma unroll
    for (int kt = 0; kt < 4; kt++) {
        size_t ai = ((size_t)T * 4 + kt) * 32 + lane;
        ah4[kt] = *(const uint4*)(g_Ahp + ai * 4);
        al4[kt] = *(const uint4*)(g_Alp + ai * 4);
    }
    const int c2 = lane * 2;
    const int r0 = lane >> 2, tig = lane & 3;
    float* ws = stg[wid];

    #pragma unroll 1
    for (int chunk = 0; chunk < 4; chunk++) {
        const int c = chunk * 64 + c2;
        // prefetch gathers for edges 0-7 (consumed after MMA)
        uint32_t pn0[8];
        #pragma unroll
        for (int j = 0; j < 8; j++)
            pn0[j] = *(const uint32_t*)(g_Pnbrh + (size_t)sIdx[wid * 16 + j] * CDIM + c);

        float acc[8][4];
        #pragma unroll
        for (int nt = 0; nt < 8; nt++)
            #pragma unroll
            for (int q = 0; q < 4; q++) acc[nt][q] = 0.f;
        #pragma unroll
        for (int kt = 0; kt < 4; kt++) {
            #pragma unroll
            for (int nt = 0; nt < 8; nt++) {
                const int ct = chunk * 8 + nt;
                const size_t bi = ((size_t)ct * 4 + kt) * 32 + lane;
                uint2 bh = *(const uint2*)(g_Whp + bi * 2);
                uint2 bl = *(const uint2*)(g_Wlp + bi * 2);
                mma16816(acc[nt], ah4[kt], bh);
                mma16816(acc[nt], ah4[kt], bl);
                mma16816(acc[nt], al4[kt], bh);
            }
        }
        // stage C: c0,c1 -> (r0, nt*8 + tig*2), c2,c3 -> (r0+8, ...)
        #pragma unroll
        for (int nt = 0; nt < 8; nt++) {
            *(float2*)(ws + r0 * SLD + nt * 8 + tig * 2)       = make_float2(acc[nt][0], acc[nt][1]);
            *(float2*)(ws + (r0 + 8) * SLD + nt * 8 + tig * 2) = make_float2(acc[nt][2], acc[nt][3]);
        }
        __syncwarp();

        // prefetch gathers for edges 8-15
        uint32_t pn1[8];
        #pragma unroll
        for (int j = 0; j < 8; j++)
            pn1[j] = *(const uint32_t*)(g_Pnbrh + (size_t)sIdx[wid * 16 + 8 + j] * CDIM + c);

        const float bc0 = sB[c], bc1 = sB[c + 1];
        float s0 = 0.f, q0 = 0.f, s1 = 0.f, q1 = 0.f;
        #pragma unroll
        for (int j = 0; j < 16; j++) {
            int e = er0 + j;
            int a = e / MNBR; if (a >= N) a = N - 1;
            uint32_t psu = *(const uint32_t*)(g_Pselfh + (size_t)a * CDIM + c);
            uint32_t pnu = (j < 8) ? pn0[j] : pn1[j - 8];
            float2 pn = __half22float2(*(__half2*)&pnu);
            float2 ps = __half22float2(*(__half2*)&psu);
            float v0 = ws[j * SLD + c2]     + pn.x + ps.x + bc0;
            float v1 = ws[j * SLD + c2 + 1] + pn.y + ps.y + bc1;
            __half2 h2 = __floats2half2_rn(v0, v1);
            if (e < Ntot) {
                *(__half2*)(g_gatedh + (size_t)e * CDIM + c) = h2;
                float2 f = __half22float2(h2);
                s0 += f.x; q0 += f.x * f.x; s1 += f.y; q1 += f.y * f.y;
            }
        }
        atomicAdd(&g_sum1[c], s0);     atomicAdd(&g_sq1[c], q0);
        atomicAdd(&g_sum1[c + 1], s1); atomicAdd(&g_sq1[c + 1], q1);
        __syncwarp();
    }
}

__global__ void k_fin1(const float* __restrict__ gm, const float* __restrict__ bt, float ic) {
    int c = threadIdx.x;
    float mean = g_sum1[c] * ic, var = g_sq1[c] * ic - mean * mean;
    float sc = gm[c] * rsqrtf(var + 1e-5f);
    g_scale1[c] = sc; g_shift1[c] = bt[c] - mean * sc;
}
__global__ void __launch_bounds__(256) k_sum(int N) {
    const int p = threadIdx.x & 63, g = threadIdx.x >> 6, n0 = blockIdx.x * 32;
    const float scf0 = g_scale1[2 * p], shf0 = g_shift1[2 * p];
    const float scf1 = g_scale1[2 * p + 1], shf1 = g_shift1[2 * p + 1];
    const float scc0 = g_scale1[128 + 2 * p], shc0 = g_shift1[128 + 2 * p];
    const float scc1 = g_scale1[128 + 2 * p + 1], shc1 = g_shift1[128 + 2 * p + 1];
    float ls0 = 0.f, lq0 = 0.f, ls1 = 0.f, lq1 = 0.f;
    for (int a = g; a < 32; a += 4) {
        const int n = n0 + a;
        if (n >= N) break;
        const __half* row = g_gatedh + (size_t)n * MNBR * CDIM;
        float a0 = 0.f, a1 = 0.f;
        #pragma unroll
        for (int m = 0; m < MNBR; m++) {
            float2 hf = __half22float2(*(const __half2*)(row + (size_t)m * CDIM + 2 * p));
            float2 hc = __half22float2(*(const __half2*)(row + (size_t)m * CDIM + 128 + 2 * p));
            float gf0 = hf.x * scf0 + shf0, gf1 = hf.y * scf1 + shf1;
            float gc0 = hc.x * scc0 + shc0, gc1 = hc.y * scc1 + shc1;
            a0 += (1.f / (1.f + expf(-gf0))) * (gc0 > 0.f ? gc0 : 0.f);
            a1 += (1.f / (1.f + expf(-gf1))) * (gc1 > 0.f ? gc1 : 0.f);
        }
        *(float2*)(g_nbrsum + (size_t)n * FDIM + 2 * p) = make_float2(a0, a1);
        ls0 += a0; lq0 += a0 * a0; ls1 += a1; lq1 += a1 * a1;
    }
    atomicAdd(&g_sum2[2 * p], ls0);     atomicAdd(&g_sq2[2 * p], lq0);
    atomicAdd(&g_sum2[2 * p + 1], ls1); atomicAdd(&g_sq2[2 * p + 1], lq1);
}
__global__ void k_fin2(const float* __restrict__ gm, const float* __restrict__ bt, float ic) {
    int c = threadIdx.x;
    float mean = g_sum2[c] * ic, var = g_sq2[c] * ic - mean * mean;
    float sc = gm[c] * rsqrtf(var + 1e-5f);
    g_scale2[c] = sc; g_shift2[c] = bt[c] - mean * sc;
}
__global__ void k_out(const float* __restrict__ atom, float* __restrict__ out, int total) {
    int i = blockIdx.x * blockDim.x + threadIdx.x;
    if (i < total) {
        int f = i & 127;
        float v = atom[i] + g_nbrsum[i] * g_scale2[f] + g_shift2[f];
        out[i] = v > 0.f ? v : 0.f;
    }
}

extern "C" void kernel_launch(void* const* d_in, const int* in_sizes, int n_in,
                              void* d_out, int out_size) {
    const float* atom = (const float*)d_in[0];
    const float* nbr  = (const float*)d_in[1];
    const void*  idx  = d_in[2];
    const float* W    = (const float*)d_in[3];
    const float* b    = (const float*)d_in[4];
    const float* g1   = (const float*)d_in[5];
    const float* b1   = (const float*)d_in[6];
    const float* g2   = (const float*)d_in[7];
    const float* b2   = (const float*)d_in[8];
    float* out = (float*)d_out;
    const int N = in_sizes[0] / FDIM;
    const int Ntot = N * MNBR;
    const int nA = ((Ntot + 15) / 16) * 128;   // A-pack thread count

    const int smP = OSTG + 16 * 320 * 4;
    static int configured = 0;
    if (!configured) {
        cudaFuncSetAttribute(k_proj, cudaFuncAttributeMaxDynamicSharedMemorySize, smP);
        configured = 1;
    }

    k_init<<<(Ntot + 255) / 256, 256>>>(idx, Ntot);                  // 1
    k_prep<<<(nA + 4096 + 255) / 256, 256>>>(nbr, W, nA, Ntot);      // 2
    dim3 gp((N + 127) / 128, 2);
    k_proj<<<gp, 512, smP>>>(atom, W, N);                            // 3
    k_edge<<<(Ntot + 63) / 64, 128>>>(b, N, Ntot);                   // 4 <- ncu slot
    k_fin1<<<1, CDIM>>>(g1, b1, 1.f / ((float)N * (float)MNBR));     // 5
    k_sum<<<(N + 31) / 32, 256>>>(N);                                // 6
    k_fin2<<<1, FDIM>>>(g2, b2, 1.f / (float)N);                     // 7
    k_out<<<((size_t)N * FDIM + 255) / 256, 256>>>(atom, out, N * FDIM);
}